// round 12
// baseline (speedup 1.0000x reference)
#include <cuda_runtime.h>
#include <cuda_bf16.h>
#include <cstdint>

constexpr int TIMESTEPS = 1000;
constexpr int B = 4;
constexpr int N = 2048;                                // power of two
constexpr long long E = (long long)N * (N - 1) / 2;    // 2,096,128
constexpr int EI = (int)E;
constexpr int QTOT = B * EI;                           // total q elements (fits int)
constexpr int NBLK = B * (N / 2);                      // 4096 blocks
constexpr int NTHR = 256;

// Cross-block reduction scratch. g_count self-resets (atomicInc wrap) -> graph-replay safe.
__device__ float        g_partials[NBLK];
__device__ unsigned int g_count = 0;

struct Consts { float flip_t, omt, qt00, qt01, qt10, qt11; };

__device__ __forceinline__ float ex2(float x) {
    float r; asm("ex2.approx.f32 %0, %1;" : "=f"(r) : "f"(x)); return r;
}
__device__ __forceinline__ float rcp(float x) {
    float r; asm("rcp.approx.f32 %0, %1;" : "=f"(r) : "f"(x)); return r;
}
// 16B global->shared async copy, L1-bypass (cg).
__device__ __forceinline__ void cpa16(uint32_t dst, const void* src) {
    asm volatile("cp.async.cg.shared.global [%0], [%1], 16;" :: "r"(dst), "l"(src));
}

// Per-element loss term: qt via 4-entry LUT on (a!=0, x1); MUFU softplus.
__device__ __forceinline__ float term(int a, float uu, float x, const Consts& c) {
    bool  ab = (a != 0);
    float pa = ab ? c.omt : c.flip_t;          // Qt[t][a, 1]
    bool  x1 = uu < pa;                        // sampled bit
    float q0 = ab ? c.qt10 : c.qt00;
    float q1 = ab ? c.qt11 : c.qt01;
    float qt = x1 ? q1 : q0;
    float sp = __logf(1.0f + __expf(-fabsf(x)));   // log1p(exp(-|x|))
    return fmaf(-x, qt, fmaxf(x, 0.0f) + sp);
}

__device__ __forceinline__ float term4(int4 A, float4 U, const float* qp, const Consts& c) {
    return term(A.x, U.x, qp[0], c) + term(A.y, U.y, qp[1], c)
         + term(A.z, U.z, qp[2], c) + term(A.w, U.w, qp[3], c);
}

// One CTA per (b,k): rows i=k (iA<=1023) and i=N-1-k (iB in [1024,2047]).
// Two cp.async groups: group0 = row-B streams, group1 = row-A; row-B compute
// overlaps row-A copies. Compute uses 4-element thread groups: LDS.128 for
// adj/u (aligned by construction), scalar LDS from one hoisted base for q.
__global__ __launch_bounds__(NTHR, 6)
void loss_kernel(const int* __restrict__ adj, const int* __restrict__ t,
                 const float* __restrict__ u, const float* __restrict__ q,
                 float* __restrict__ out) {
    __shared__ alignas(16) int   s_adj[2056];   // packed: rowA chunks then rowB chunks
    __shared__ alignas(16) float s_u[2056];
    __shared__ alignas(16) float s_q[2064];     // 16B-rounded on both rows
    __shared__ float warp_sums[8];
    __shared__ bool  is_last;

    const int tid = threadIdx.x;
    const int wb  = tid & ~31;          // warp base (uniform predicates)
    const int bidx = blockIdx.x;
    const int b    = bidx >> 10;        // / (N/2)
    const int k    = bidx & 1023;       // % (N/2)

    const int iA = k;
    const int iB = N - 1 - k;
    const int rowbaseA = ((b << 11) + iA) << 11;     // (b*N+iA)*N
    const int rowbaseB = ((b << 11) + iB) << 11;
    const int qrowA = b * EI + ((iA * (iA - 1)) >> 1);
    const int qrowB = b * EI + ((iB * (iB - 1)) >> 1);

    // Chunk geometry (16B = 4 elements per chunk). adj/u chunks stay inside the
    // 2048-element row; q chunk addresses are clamped at the buffer end (the
    // clamp is a no-op for every chunk whose data is actually consumed).
    const int cA   = (iA + 3) >> 2;                  // <= 256
    const int cB   = (iB + 3) >> 2;                  // in [256, 512]
    const int cA4  = cA << 2;
    const int galA = qrowA & ~3, ofsA = qrowA & 3;
    const int galB = qrowB & ~3, ofsB = qrowB & 3;
    const int cqA  = (iA + ofsA + 3) >> 2;           // <= 257
    const int cqB  = (iB + ofsB + 3) >> 2;           // in [256, 513]
    const int cqA4 = cqA << 2;

    const uint32_t sa = (uint32_t)__cvta_generic_to_shared(s_adj);
    const uint32_t su = (uint32_t)__cvta_generic_to_shared(s_u);
    const uint32_t sq = (uint32_t)__cvta_generic_to_shared(s_q);
    const uint32_t saB = sa + cA4 * 4,  suB = su + cA4 * 4,  sqB = sq + cqA4 * 4;

    const char* gaB = (const char*)(adj + rowbaseB);
    const char* guB = (const char*)(u   + rowbaseB);
    const char* gaA = (const char*)(adj + rowbaseA);
    const char* guA = (const char*)(u   + rowbaseA);

    // ---- group 0: row B streams (big row first) ----
    cpa16(saB + tid * 16, gaB + tid * 16);                       // cB >= 256: unconditional
    cpa16(suB + tid * 16, guB + tid * 16);
    cpa16(sqB + tid * 16, q + (galB + (tid << 2)));              // cqB >= 256, in-bounds
    if (256 + wb < cB) {                                         // warp-uniform
        int cc = min(tid + 256, cB - 1);                         // dup-clamp: benign
        cpa16(saB + cc * 16, gaB + cc * 16);
        cpa16(suB + cc * 16, guB + cc * 16);
    }
    if (256 + wb < cqB) {
        int cc = min(tid + 256, cqB - 1);
        int gb = min(galB + (cc << 2), QTOT - 4);                // buffer-end clamp
        cpa16(sqB + cc * 16, q + gb);
    }
    if (tid == 0 && cqB > 512) {                                 // rare 513th chunk
        int gb = min(galB + 2048, QTOT - 4);
        cpa16(sqB + 512 * 16, q + gb);
    }
    asm volatile("cp.async.commit_group;" ::: "memory");

    // ---- group 1: row A streams ----
    if (wb < cA) {
        int cc = min(tid, cA - 1);
        cpa16(sa + cc * 16, gaA + cc * 16);
        cpa16(su + cc * 16, guA + cc * 16);
    }
    if (wb < cqA) {
        int cc = min(tid, cqA - 1);
        int gb = min(galA + (cc << 2), QTOT - 4);
        cpa16(sq + cc * 16, q + gb);
    }
    if (tid == 0 && cqA > 256) {
        int gb = min(galA + 1024, QTOT - 4);
        cpa16(sq + 256 * 16, q + gb);
    }
    asm volatile("cp.async.commit_group;" ::: "memory");

    // Per-thread fp32 constants (MUFU) — computed while copies are in flight.
    Consts c;
    {
        const float L2_098 = -0.0291463173f;               // log2(0.98)
        int   tb = t[b];
        float pt = ex2((float)(tb + 1) * L2_098);          // 0.98^(t+1)
        int   tm1 = (tb + TIMESTEPS - 1) % TIMESTEPS;      // Qt[t-1] wraps at t=0
        float pp = ex2((float)(tm1 + 1) * L2_098);
        c.flip_t = 0.5f - 0.5f * pt;
        c.omt    = 0.5f + 0.5f * pt;
        float flip_p = 0.5f - 0.5f * pp;
        float omp    = 0.5f + 0.5f * pp;
        float r_omt  = rcp(c.omt);
        float r_flip = rcp(c.flip_t);
        // qt[ab][x1] = Qt0[x1,1] * Qt[t-1][ab,1] / Qt[t][ab,x1]
        c.qt00 = 0.01f * flip_p * r_omt;
        c.qt01 = 0.99f * flip_p * r_flip;
        c.qt10 = 0.01f * omp    * r_flip;
        c.qt11 = 0.99f * omp    * r_omt;
    }

    // ---- wait for row B only; row A still streaming ----
    asm volatile("cp.async.wait_group 1;" ::: "memory");
    __syncthreads();

    float s = 0.0f;

    {   // row B: 4-element vector groups
        const int nfB = iB >> 2, remB = iB & 3;          // nfB in [256, 511]
        const int4*   aB4 = reinterpret_cast<const int4*>(s_adj + cA4);
        const float4* uB4 = reinterpret_cast<const float4*>(s_u + cA4);
        const float*  qB  = s_q + cqA4 + ofsB;

        // group 0: always full (tid < 256 <= nfB)
        s += term4(aB4[tid], uB4[tid], qB + (tid << 2), c);
        // group 1: predicated (divergent in at most one warp)
        const int g1 = tid + 256;
        if (g1 < nfB)
            s += term4(aB4[g1], uB4[g1], qB + (g1 << 2), c);
        // tail: <= 3 threads
        if (tid < remB) {
            int e = (nfB << 2) + tid;
            s += term(s_adj[cA4 + e], s_u[cA4 + e], qB[e], c);
        }
    }

    // ---- row A ----
    asm volatile("cp.async.wait_group 0;" ::: "memory");
    __syncthreads();

    {   // row A: 4-element vector groups (nfA <= 255)
        const int nfA = iA >> 2, remA = iA & 3;
        const int4*   aA4 = reinterpret_cast<const int4*>(s_adj);
        const float4* uA4 = reinterpret_cast<const float4*>(s_u);
        const float*  qA  = s_q + ofsA;

        if (tid < nfA)
            s += term4(aA4[tid], uA4[tid], qA + (tid << 2), c);
        if (tid < remA) {
            int e = (nfA << 2) + tid;
            s += term(s_adj[e], s_u[e], qA[e], c);
        }
    }

    // Block reduction
    #pragma unroll
    for (int off = 16; off; off >>= 1) s += __shfl_down_sync(0xffffffffu, s, off);
    const int lane = tid & 31, wid = tid >> 5;
    if (lane == 0) warp_sums[wid] = s;
    __syncthreads();
    if (wid == 0) {
        s = (lane < 8) ? warp_sums[lane] : 0.0f;
        #pragma unroll
        for (int off = 4; off; off >>= 1) s += __shfl_down_sync(0xffffffffu, s, off);
        if (lane == 0) g_partials[bidx] = s;
    }

    // Last-block-standing final reduction (counter wraps to 0 -> replayable)
    __threadfence();
    if (tid == 0) {
        unsigned v = atomicInc(&g_count, NBLK - 1);
        is_last = (v == NBLK - 1);
    }
    __syncthreads();
    if (is_last) {
        float acc = 0.0f;
        for (int idx = tid; idx < NBLK; idx += NTHR) acc += g_partials[idx];
        #pragma unroll
        for (int off = 16; off; off >>= 1) acc += __shfl_down_sync(0xffffffffu, acc, off);
        if (lane == 0) warp_sums[wid] = acc;
        __syncthreads();
        if (wid == 0) {
            acc = (lane < 8) ? warp_sums[lane] : 0.0f;
            #pragma unroll
            for (int off = 4; off; off >>= 1) acc += __shfl_down_sync(0xffffffffu, acc, off);
            if (lane == 0) out[0] = acc * (1.0f / (float)(B * E));
        }
    }
}

extern "C" void kernel_launch(void* const* d_in, const int* in_sizes, int n_in,
                              void* d_out, int out_size) {
    // metadata order: adj_start (int32), t (int32), u (f32), q_approx (f32)
    const int*   adj = (const int*)d_in[0];
    const int*   t   = (const int*)d_in[1];
    const float* u   = (const float*)d_in[2];
    const float* q   = (const float*)d_in[3];
    float* out = (float*)d_out;

    // Context-level (not stream) call: capture-legal, deterministic, no alloc.
    cudaFuncSetAttribute(loss_kernel,
                         cudaFuncAttributePreferredSharedMemoryCarveout,
                         cudaSharedmemCarveoutMaxShared);

    loss_kernel<<<NBLK, NTHR>>>(adj, t, u, q, out);
}

// round 14
// speedup vs baseline: 1.0141x; 1.0141x over previous
#include <cuda_runtime.h>
#include <cuda_bf16.h>
#include <cstdint>

constexpr int TIMESTEPS = 1000;
constexpr int B = 4;
constexpr int N = 2048;                                // power of two
constexpr long long E = (long long)N * (N - 1) / 2;    // 2,096,128
constexpr int EI = (int)E;
constexpr int QTOT = B * EI;                           // total q elements (fits int)
constexpr int NPAIR = B * (N / 2);                     // 4096 work pairs
constexpr int GRID = 592;                              // 148 SMs x 4 CTAs
constexpr int NTHR = 256;

// Per-buffer SMEM word layout: adj[2056] | u[2056] | q[2064]  = 6176 words
constexpr int W_U   = 2056;
constexpr int W_Q   = 4112;
constexpr int BUFW  = 6176;
constexpr int BUFB  = BUFW * 4;                        // 24704 bytes, 16B-aligned
constexpr int SMEM_DYN = 2 * BUFB;                     // 49408 bytes

// Cross-block reduction scratch. g_count self-resets (atomicInc wrap) -> graph-replay safe.
__device__ float        g_partials[GRID];
__device__ unsigned int g_count = 0;

struct Consts { float flip_t, omt, qt00, qt01, qt10, qt11; };

__device__ __forceinline__ float ex2(float x) {
    float r; asm("ex2.approx.f32 %0, %1;" : "=f"(r) : "f"(x)); return r;
}
__device__ __forceinline__ float rcp(float x) {
    float r; asm("rcp.approx.f32 %0, %1;" : "=f"(r) : "f"(x)); return r;
}
// 16B global->shared async copy, L1-bypass (cg). (No L2 policy: descriptor
// cache-hint forms trap with illegal-instruction on sm_103a.)
__device__ __forceinline__ void cpa16(uint32_t dst, const void* src) {
    asm volatile("cp.async.cg.shared.global [%0], [%1], 16;" :: "r"(dst), "l"(src));
}

// Per-element loss term: qt via 4-entry LUT on (a!=0, x1); MUFU softplus.
__device__ __forceinline__ float term(int a, float uu, float x, const Consts& c) {
    bool  ab = (a != 0);
    float pa = ab ? c.omt : c.flip_t;          // Qt[t][a, 1]
    bool  x1 = uu < pa;                        // sampled bit
    float q0 = ab ? c.qt10 : c.qt00;
    float q1 = ab ? c.qt11 : c.qt01;
    float qt = x1 ? q1 : q0;
    float sp = __logf(1.0f + __expf(-fabsf(x)));   // log1p(exp(-|x|))
    return fmaf(-x, qt, fmaxf(x, 0.0f) + sp);
}

__device__ __forceinline__ float term4(int4 A, float4 U, const float* qp, const Consts& c) {
    return term(A.x, U.x, qp[0], c) + term(A.y, U.y, qp[1], c)
         + term(A.z, U.z, qp[2], c) + term(A.w, U.w, qp[3], c);
}

// Pair geometry: pair pid = (b, k) covers rows i=k (iA<=1023) and i=N-1-k
// (iB in [1024, 2047]); iA+iB = 2047 elements.
struct Geom {
    int iA, iB, rowbaseA, rowbaseB, cA, cB, cA4;
    int galA, ofsA, galB, ofsB, cqA, cqB, cqA4;
    int b;
};
__device__ __forceinline__ Geom mk_geom(int pid) {
    Geom g;
    g.b  = pid >> 10;
    int k = pid & 1023;
    g.iA = k;  g.iB = N - 1 - k;
    g.rowbaseA = ((g.b << 11) + g.iA) << 11;
    g.rowbaseB = ((g.b << 11) + g.iB) << 11;
    int qrowA = g.b * EI + ((g.iA * (g.iA - 1)) >> 1);
    int qrowB = g.b * EI + ((g.iB * (g.iB - 1)) >> 1);
    g.cA  = (g.iA + 3) >> 2;  g.cB = (g.iB + 3) >> 2;  g.cA4 = g.cA << 2;
    g.galA = qrowA & ~3;  g.ofsA = qrowA & 3;
    g.galB = qrowB & ~3;  g.ofsB = qrowB & 3;
    g.cqA = (g.iA + g.ofsA + 3) >> 2;
    g.cqB = (g.iB + g.ofsB + 3) >> 2;
    g.cqA4 = g.cqA << 2;
    return g;
}

// Stage one pair into the SMEM buffer at shared-address s0 (cp.async only; the
// caller commits). adj/u chunks stay inside their 2048-element rows; q chunk
// addresses are clamped at the buffer end (no-op for consumed chunks).
__device__ __forceinline__ void stage_pair(const Geom& g,
                                           const int* __restrict__ adj,
                                           const float* __restrict__ u,
                                           const float* __restrict__ q,
                                           uint32_t s0, int tid, int wb) {
    const uint32_t sa = s0, su = s0 + W_U * 4, sq = s0 + W_Q * 4;
    const uint32_t saB = sa + g.cA4 * 4, suB = su + g.cA4 * 4, sqB = sq + g.cqA4 * 4;
    const char* gaB = (const char*)(adj + g.rowbaseB);
    const char* guB = (const char*)(u   + g.rowbaseB);
    const char* gaA = (const char*)(adj + g.rowbaseA);
    const char* guA = (const char*)(u   + g.rowbaseA);

    // row B streams (cB, cqB >= 256 -> first slots unconditional)
    cpa16(saB + tid * 16, gaB + tid * 16);
    cpa16(suB + tid * 16, guB + tid * 16);
    cpa16(sqB + tid * 16, q + (g.galB + (tid << 2)));
    if (256 + wb < g.cB) {                       // warp-uniform
        int cc = min(tid + 256, g.cB - 1);       // dup-clamp: benign
        cpa16(saB + cc * 16, gaB + cc * 16);
        cpa16(suB + cc * 16, guB + cc * 16);
    }
    if (256 + wb < g.cqB) {
        int cc = min(tid + 256, g.cqB - 1);
        int gb = min(g.galB + (cc << 2), QTOT - 4);
        cpa16(sqB + cc * 16, q + gb);
    }
    if (tid == 0 && g.cqB > 512) {               // rare 513th chunk
        int gb = min(g.galB + 2048, QTOT - 4);
        cpa16(sqB + 512 * 16, q + gb);
    }
    // row A streams
    if (wb < g.cA) {
        int cc = min(tid, g.cA - 1);
        cpa16(sa + cc * 16, gaA + cc * 16);
        cpa16(su + cc * 16, guA + cc * 16);
    }
    if (wb < g.cqA) {
        int cc = min(tid, g.cqA - 1);
        int gb = min(g.galA + (cc << 2), QTOT - 4);
        cpa16(sq + cc * 16, q + gb);
    }
    if (tid == 0 && g.cqA > 256) {
        int gb = min(g.galA + 1024, QTOT - 4);
        cpa16(sq + 256 * 16, q + gb);
    }
}

// Compute one staged pair from SMEM.
__device__ __forceinline__ float compute_pair(const Geom& g, const char* sbuf,
                                              const int* __restrict__ t, int tid) {
    Consts c;
    {
        const float L2_098 = -0.0291463173f;               // log2(0.98)
        int   tb = t[g.b];
        float pt = ex2((float)(tb + 1) * L2_098);          // 0.98^(t+1)
        int   tm1 = (tb + TIMESTEPS - 1) % TIMESTEPS;      // Qt[t-1] wraps at t=0
        float pp = ex2((float)(tm1 + 1) * L2_098);
        c.flip_t = 0.5f - 0.5f * pt;
        c.omt    = 0.5f + 0.5f * pt;
        float flip_p = 0.5f - 0.5f * pp;
        float omp    = 0.5f + 0.5f * pp;
        float r_omt  = rcp(c.omt);
        float r_flip = rcp(c.flip_t);
        // qt[ab][x1] = Qt0[x1,1] * Qt[t-1][ab,1] / Qt[t][ab,x1]
        c.qt00 = 0.01f * flip_p * r_omt;
        c.qt01 = 0.99f * flip_p * r_flip;
        c.qt10 = 0.01f * omp    * r_flip;
        c.qt11 = 0.99f * omp    * r_omt;
    }

    const int*   s_adj = (const int*)sbuf;
    const float* s_u   = (const float*)(sbuf + W_U * 4);
    const float* s_q   = (const float*)(sbuf + W_Q * 4);

    float s = 0.0f;
    {   // row B: 4-element vector groups (nfB in [256, 511])
        const int nfB = g.iB >> 2, remB = g.iB & 3;
        const int4*   aB4 = reinterpret_cast<const int4*>(s_adj + g.cA4);
        const float4* uB4 = reinterpret_cast<const float4*>(s_u + g.cA4);
        const float*  qB  = s_q + g.cqA4 + g.ofsB;
        s += term4(aB4[tid], uB4[tid], qB + (tid << 2), c);      // always full
        const int g1 = tid + 256;
        if (g1 < nfB) s += term4(aB4[g1], uB4[g1], qB + (g1 << 2), c);
        if (tid < remB) {
            int e = (nfB << 2) + tid;
            s += term(s_adj[g.cA4 + e], s_u[g.cA4 + e], qB[e], c);
        }
    }
    {   // row A: 4-element vector groups (nfA <= 255)
        const int nfA = g.iA >> 2, remA = g.iA & 3;
        const int4*   aA4 = reinterpret_cast<const int4*>(s_adj);
        const float4* uA4 = reinterpret_cast<const float4*>(s_u);
        const float*  qA  = s_q + g.ofsA;
        if (tid < nfA) s += term4(aA4[tid], uA4[tid], qA + (tid << 2), c);
        if (tid < remA) {
            int e = (nfA << 2) + tid;
            s += term(s_adj[e], s_u[e], qA[e], c);
        }
    }
    return s;
}

// Persistent CTAs (grid = 148x4), double-buffered cp.async pipeline across
// pairs: stage pair j+1, wait for pair j, compute pair j. The DRAM fill
// latency is paid once per CTA instead of once per pair.
__global__ __launch_bounds__(NTHR, 4)
void loss_kernel(const int* __restrict__ adj, const int* __restrict__ t,
                 const float* __restrict__ u, const float* __restrict__ q,
                 float* __restrict__ out) {
    extern __shared__ char smem[];
    __shared__ float warp_sums[8];
    __shared__ bool  is_last;

    const int tid  = threadIdx.x;
    const int wb   = tid & ~31;
    const int bidx = blockIdx.x;
    const uint32_t s0 = (uint32_t)__cvta_generic_to_shared(smem);

    const int npairs = (NPAIR - 1 - bidx) / GRID + 1;   // 7 or 6

    int  pid = bidx;
    Geom gcur = mk_geom(pid);
    stage_pair(gcur, adj, u, q, s0, tid, wb);
    asm volatile("cp.async.commit_group;" ::: "memory");

    float s = 0.0f;
    for (int j = 0; j < npairs; ++j) {
        if (j) __syncthreads();                          // prev compute done before restage
        Geom gnext;
        if (j + 1 < npairs) {
            gnext = mk_geom(pid + GRID);
            stage_pair(gnext, adj, u, q, s0 + ((j + 1) & 1) * BUFB, tid, wb);
        }
        asm volatile("cp.async.commit_group;" ::: "memory");   // may be empty: keeps counts aligned
        asm volatile("cp.async.wait_group 1;" ::: "memory");   // pair j ready; j+1 in flight
        __syncthreads();
        s += compute_pair(gcur, smem + (j & 1) * BUFB, t, tid);
        gcur = gnext;
        pid += GRID;
    }
    asm volatile("cp.async.wait_group 0;" ::: "memory");  // drain before exit

    // Block reduction
    #pragma unroll
    for (int off = 16; off; off >>= 1) s += __shfl_down_sync(0xffffffffu, s, off);
    const int lane = tid & 31, wid = tid >> 5;
    if (lane == 0) warp_sums[wid] = s;
    __syncthreads();
    if (wid == 0) {
        s = (lane < 8) ? warp_sums[lane] : 0.0f;
        #pragma unroll
        for (int off = 4; off; off >>= 1) s += __shfl_down_sync(0xffffffffu, s, off);
        if (lane == 0) g_partials[bidx] = s;
    }

    // Last-block-standing final reduction (counter wraps to 0 -> replayable)
    __threadfence();
    if (tid == 0) {
        unsigned v = atomicInc(&g_count, GRID - 1);
        is_last = (v == GRID - 1);
    }
    __syncthreads();
    if (is_last) {
        float acc = 0.0f;
        for (int idx = tid; idx < GRID; idx += NTHR) acc += g_partials[idx];
        #pragma unroll
        for (int off = 16; off; off >>= 1) acc += __shfl_down_sync(0xffffffffu, acc, off);
        if (lane == 0) warp_sums[wid] = acc;
        __syncthreads();
        if (wid == 0) {
            acc = (lane < 8) ? warp_sums[lane] : 0.0f;
            #pragma unroll
            for (int off = 4; off; off >>= 1) acc += __shfl_down_sync(0xffffffffu, acc, off);
            if (lane == 0) out[0] = acc * (1.0f / (float)(B * E));
        }
    }
}

extern "C" void kernel_launch(void* const* d_in, const int* in_sizes, int n_in,
                              void* d_out, int out_size) {
    // metadata order: adj_start (int32), t (int32), u (f32), q_approx (f32)
    const int*   adj = (const int*)d_in[0];
    const int*   t   = (const int*)d_in[1];
    const float* u   = (const float*)d_in[2];
    const float* q   = (const float*)d_in[3];
    float* out = (float*)d_out;

    // Function attributes (context-level, capture-legal, no allocation):
    // 49.4KB dynamic SMEM needs opt-in; max carveout fits 4 CTAs/SM.
    cudaFuncSetAttribute(loss_kernel,
                         cudaFuncAttributeMaxDynamicSharedMemorySize, SMEM_DYN);
    cudaFuncSetAttribute(loss_kernel,
                         cudaFuncAttributePreferredSharedMemoryCarveout,
                         cudaSharedmemCarveoutMaxShared);

    loss_kernel<<<GRID, NTHR, SMEM_DYN>>>(adj, t, u, q, out);
}